// round 1
// baseline (speedup 1.0000x reference)
#include <cuda_runtime.h>
#include <math.h>

// ----------------------------- constants ------------------------------------
#define S     2048
#define D     1024
#define HEADS 16
#define HD    64
#define E     8
#define HID   4096
#define NACT  3
#define NSLOT (S*NACT)          // 6144
#define TPE   16                // max 128-row tiles per expert (covers 2048 rows)

// ----------------------------- scratch (device globals) ---------------------
__device__ float g_xn   [S*D];
__device__ float g_qkv  [S*3*D];
__device__ float g_qr   [HEADS*S*HD];
__device__ float g_kr   [HEADS*S*HD];
__device__ float g_attn [S*D];
__device__ float g_attnP[S*D];
__device__ float g_xmid [S*D];
__device__ float g_xn2  [S*D];
__device__ float g_Q    [HD*HD];
__device__ float g_h    [(size_t)NSLOT*2*HID];   // 192 MB
__device__ float g_g    [(size_t)NSLOT*HID];     // 96 MB
__device__ float g_oslot[(size_t)NSLOT*D];       // 24 MB
__device__ int   g_counts[E];
__device__ int   g_offsets[E+1];
__device__ int   g_cursor[E];
__device__ int   g_rowmap[NSLOT];
__device__ float g_slotscale[NSLOT];
__device__ int   g_slotpos[NSLOT];
__device__ int   g_topi[S*NACT];
__device__ float g_topw[S*NACT];
__device__ float g_aux[1];

// ----------------------------- reset ----------------------------------------
__global__ void k_reset() {
    int t = threadIdx.x;
    if (t < E) g_counts[t] = 0;
    if (t == 0) g_aux[0] = 0.f;
}

// ----------------------------- rmsnorm --------------------------------------
__global__ void k_rmsnorm(const float* __restrict__ x, float* __restrict__ o) {
    int s = blockIdx.x;
    __shared__ float red[256];
    float ss = 0.f;
    for (int d = threadIdx.x; d < D; d += 256) { float v = x[(size_t)s*D+d]; ss += v*v; }
    red[threadIdx.x] = ss; __syncthreads();
    for (int st = 128; st > 0; st >>= 1) { if (threadIdx.x < st) red[threadIdx.x] += red[threadIdx.x+st]; __syncthreads(); }
    float r = rsqrtf(red[0] * (1.f/D) + 1e-6f);
    for (int d = threadIdx.x; d < D; d += 256) o[(size_t)s*D+d] = x[(size_t)s*D+d]*r;
}

// ----------------------------- SGEMM 128x128x8 -------------------------------
// C[M,N] = A[M,K] @ B[K,N], all row-major. EPI==1: gated-residual epilogue
// (C = resid + A_elem * sigmoid(acc + bias[c]), requires K==N so A[r][c] valid).
template<int EPI>
__global__ void __launch_bounds__(256) k_sgemm(
        const float* __restrict__ A, const float* __restrict__ B, float* __restrict__ C,
        int M, int N, int K, const float* __restrict__ resid, const float* __restrict__ bias)
{
    __shared__ float As[8][136];
    __shared__ float Bs[8][128];
    int tid = threadIdx.x, tx = tid & 15, ty = tid >> 4;
    int row0 = blockIdx.y * 128, col0 = blockIdx.x * 128;
    float acc[8][8];
    #pragma unroll
    for (int i = 0; i < 8; i++)
        #pragma unroll
        for (int j = 0; j < 8; j++) acc[i][j] = 0.f;

    int am = tid >> 1, ak = (tid & 1) * 4;
    int bk = tid >> 5, bn = (tid & 31) * 4;
    const float* Ap = A + (size_t)(row0 + am) * K + ak;
    const float* Bp = B + (size_t)bk * N + col0 + bn;

    for (int kk = 0; kk < K; kk += 8) {
        float4 a4 = *(const float4*)(Ap + kk);
        float4 b4 = *(const float4*)(Bp + (size_t)kk * N);
        As[ak+0][am] = a4.x; As[ak+1][am] = a4.y; As[ak+2][am] = a4.z; As[ak+3][am] = a4.w;
        *(float4*)&Bs[bk][bn] = b4;
        __syncthreads();
        #pragma unroll
        for (int k = 0; k < 8; k++) {
            float4 a0 = *(const float4*)&As[k][ty*8];
            float4 a1 = *(const float4*)&As[k][ty*8+4];
            float4 b0 = *(const float4*)&Bs[k][tx*8];
            float4 b1 = *(const float4*)&Bs[k][tx*8+4];
            float af[8] = {a0.x,a0.y,a0.z,a0.w,a1.x,a1.y,a1.z,a1.w};
            float bf[8] = {b0.x,b0.y,b0.z,b0.w,b1.x,b1.y,b1.z,b1.w};
            #pragma unroll
            for (int i = 0; i < 8; i++)
                #pragma unroll
                for (int j = 0; j < 8; j++) acc[i][j] += af[i]*bf[j];
        }
        __syncthreads();
    }
    #pragma unroll
    for (int i = 0; i < 8; i++) {
        int r = row0 + ty*8 + i;
        #pragma unroll
        for (int j = 0; j < 8; j++) {
            int c = col0 + tx*8 + j;
            float v = acc[i][j];
            if (EPI == 1) {
                float p  = A[(size_t)r*K + c];
                float gt = 1.f / (1.f + __expf(-(v + bias[c])));
                v = resid[(size_t)r*N + c] + p * gt;
            }
            C[(size_t)r*N + c] = v;
        }
    }
}

// ----------------------------- grouped SGEMM (MoE) ---------------------------
// Rows grouped by expert via g_offsets; GATHER reads A rows through g_rowmap;
// SCALE multiplies output rows by g_slotscale.
template<bool GATHER, bool SCALE>
__global__ void __launch_bounds__(256) k_sgemm_group(
        const float* __restrict__ A, const float* __restrict__ B0, float* __restrict__ C,
        int N, int K, long long ldbE)
{
    int e = blockIdx.y / TPE, t = blockIdx.y % TPE;
    int start = g_offsets[e], end = g_offsets[e+1];
    int row0 = start + t * 128;
    if (row0 >= end) return;
    int rows = end - row0; if (rows > 128) rows = 128;
    const float* B = B0 + (size_t)e * ldbE;

    __shared__ float As[8][136];
    __shared__ float Bs[8][128];
    __shared__ int   ridx[128];
    int tid = threadIdx.x, tx = tid & 15, ty = tid >> 4;
    if (GATHER) {
        if (tid < 128) ridx[tid] = g_rowmap[row0 + min(tid, rows-1)];
    }
    __syncthreads();

    int col0 = blockIdx.x * 128;
    float acc[8][8];
    #pragma unroll
    for (int i = 0; i < 8; i++)
        #pragma unroll
        for (int j = 0; j < 8; j++) acc[i][j] = 0.f;

    int am = tid >> 1, ak = (tid & 1) * 4;
    int bk = tid >> 5, bn = (tid & 31) * 4;
    int arow = GATHER ? ridx[am] : (row0 + min(am, rows-1));
    const float* Ap = A + (size_t)arow * K + ak;
    const float* Bp = B + (size_t)bk * N + col0 + bn;

    for (int kk = 0; kk < K; kk += 8) {
        float4 a4 = *(const float4*)(Ap + kk);
        float4 b4 = *(const float4*)(Bp + (size_t)kk * N);
        As[ak+0][am] = a4.x; As[ak+1][am] = a4.y; As[ak+2][am] = a4.z; As[ak+3][am] = a4.w;
        *(float4*)&Bs[bk][bn] = b4;
        __syncthreads();
        #pragma unroll
        for (int k = 0; k < 8; k++) {
            float4 a0 = *(const float4*)&As[k][ty*8];
            float4 a1 = *(const float4*)&As[k][ty*8+4];
            float4 b0 = *(const float4*)&Bs[k][tx*8];
            float4 b1 = *(const float4*)&Bs[k][tx*8+4];
            float af[8] = {a0.x,a0.y,a0.z,a0.w,a1.x,a1.y,a1.z,a1.w};
            float bf[8] = {b0.x,b0.y,b0.z,b0.w,b1.x,b1.y,b1.z,b1.w};
            #pragma unroll
            for (int i = 0; i < 8; i++)
                #pragma unroll
                for (int j = 0; j < 8; j++) acc[i][j] += af[i]*bf[j];
        }
        __syncthreads();
    }
    #pragma unroll
    for (int i = 0; i < 8; i++) {
        int rr = ty*8 + i;
        if (rr < rows) {
            int r = row0 + rr;
            float sc = SCALE ? g_slotscale[r] : 1.f;
            #pragma unroll
            for (int j = 0; j < 8; j++) {
                int c = col0 + tx*8 + j;
                C[(size_t)r*N + c] = acc[i][j] * sc;
            }
        }
    }
}

// ----------------------------- Householder Q --------------------------------
__global__ void k_house(const float* __restrict__ vs) {
    __shared__ float Q[64][65];
    __shared__ float v[64], w[64];
    __shared__ float vn;
    int tid = threadIdx.x;  // 256
    for (int i = tid; i < 4096; i += 256) Q[i>>6][i&63] = ((i>>6)==(i&63)) ? 1.f : 0.f;
    __syncthreads();
    for (int r = 0; r < 32; r++) {
        if (tid < 64) v[tid] = vs[r*64 + tid];
        __syncthreads();
        if (tid == 0) { float s = 0.f; for (int i = 0; i < 64; i++) s += v[i]*v[i]; vn = 2.f / (s + 1e-8f); }
        if (tid < 64) { float s = 0.f; for (int i = 0; i < 64; i++) s += v[i]*Q[i][tid]; w[tid] = s; }
        __syncthreads();
        for (int i = tid; i < 4096; i += 256) { int a = i>>6, b = i&63; Q[a][b] -= vn * v[a] * w[b]; }
        __syncthreads();
    }
    for (int i = tid; i < 4096; i += 256) g_Q[i] = Q[i>>6][i&63];
}

// ----------------------------- RnRoPE ----------------------------------------
// q' = apply_rot(q @ Q^T, cos, sin) @ Q, per (token, head), for q and k.
__global__ void __launch_bounds__(256) k_rope(const float* __restrict__ rope_pos,
                                              const float* __restrict__ inv_freq) {
    int s = blockIdx.x;
    __shared__ float Q[64][65];
    __shared__ float cs[32], sn[32];
    __shared__ float vec[4][64], tv[4][64];
    int tid = threadIdx.x;
    for (int i = tid; i < 4096; i += 256) Q[i>>6][i&63] = g_Q[i];
    if (tid < 32) {
        float f = 0.f;
        if (tid < 15) f = rope_pos[s*3 + tid/5] * inv_freq[tid % 5];
        cs[tid] = cosf(f); sn[tid] = sinf(f);
    }
    __syncthreads();
    int grp = tid >> 6, lane = tid & 63;
    for (int vb = 0; vb < 32; vb += 4) {
        int vi = vb + grp;
        int h = vi >> 1, isk = vi & 1;
        const float* src = g_qkv + (size_t)s*3*D + isk*D + h*HD;
        vec[grp][lane] = src[lane];
        __syncthreads();
        // t = vec @ Q^T : t[j] = sum_d vec[d]*Q[j][d]
        float t0 = 0.f, t1 = 0.f;
        #pragma unroll
        for (int d = 0; d < 64; d += 2) { t0 += vec[grp][d]*Q[lane][d]; t1 += vec[grp][d+1]*Q[lane][d+1]; }
        tv[grp][lane] = t0 + t1;
        __syncthreads();
        int p = lane & 31;
        float c = cs[p], si = sn[p];
        float rr = (lane < 32) ? (tv[grp][lane]*c - tv[grp][lane+32]*si)
                               : (tv[grp][lane]*c + tv[grp][lane-32]*si);
        __syncthreads();
        vec[grp][lane] = rr;
        __syncthreads();
        // out[j] = sum_d rot[d]*Q[d][j]
        float o0 = 0.f, o1 = 0.f;
        #pragma unroll
        for (int d = 0; d < 64; d += 2) { o0 += vec[grp][d]*Q[d][lane]; o1 += vec[grp][d+1]*Q[d+1][lane]; }
        float* dst = (isk ? g_kr : g_qr) + ((size_t)h*S + s)*HD;
        dst[lane] = o0 + o1;
        __syncthreads();
    }
}

// ----------------------------- flash attention -------------------------------
// grid (S/64, HEADS); block 256. Bq=64, Bk=32. q row in registers.
__global__ void __launch_bounds__(256) k_attn() {
    int qt = blockIdx.x, h = blockIdx.y;
    __shared__ float Ks[32][68];
    __shared__ float Vs[32][68];
    __shared__ float Ps[64][33];
    int tid = threadIdx.x, r = tid >> 2, g = tid & 3;

    float qreg[64];
    const float* qrow = g_qr + ((size_t)h*S + qt*64 + r)*HD;
    #pragma unroll
    for (int d = 0; d < 64; d += 4) {
        float4 q4 = *(const float4*)(qrow + d);
        qreg[d] = q4.x; qreg[d+1] = q4.y; qreg[d+2] = q4.z; qreg[d+3] = q4.w;
    }
    float m = -1e30f, l = 0.f, o[16];
    #pragma unroll
    for (int c = 0; c < 16; c++) o[c] = 0.f;

    for (int kt = 0; kt < S; kt += 32) {
        for (int i = tid; i < 32*64; i += 256) {
            int kr = i >> 6, kd = i & 63;
            Ks[kr][kd] = g_kr[((size_t)h*S + kt + kr)*HD + kd];
            Vs[kr][kd] = g_qkv[(size_t)(kt+kr)*3*D + 2*D + h*HD + kd];
        }
        __syncthreads();
        float sc[8];
        #pragma unroll
        for (int kk = 0; kk < 8; kk++) sc[kk] = 0.f;
        #pragma unroll
        for (int d = 0; d < 64; d += 4) {
            #pragma unroll
            for (int kk = 0; kk < 8; kk++) {
                int k = g*8 + kk;
                float4 k4 = *(const float4*)&Ks[k][d];
                sc[kk] += qreg[d]*k4.x + qreg[d+1]*k4.y + qreg[d+2]*k4.z + qreg[d+3]*k4.w;
            }
        }
        float mx = -1e30f;
        #pragma unroll
        for (int kk = 0; kk < 8; kk++) { sc[kk] *= 0.125f; mx = fmaxf(mx, sc[kk]); }
        mx = fmaxf(mx, __shfl_xor_sync(0xffffffffu, mx, 1));
        mx = fmaxf(mx, __shfl_xor_sync(0xffffffffu, mx, 2));
        float mnew = fmaxf(m, mx);
        float corr = __expf(m - mnew);
        float ps = 0.f;
        #pragma unroll
        for (int kk = 0; kk < 8; kk++) {
            float p = __expf(sc[kk] - mnew);
            Ps[r][g*8+kk] = p; ps += p;
        }
        ps += __shfl_xor_sync(0xffffffffu, ps, 1);
        ps += __shfl_xor_sync(0xffffffffu, ps, 2);
        l = l*corr + ps; m = mnew;
        #pragma unroll
        for (int c = 0; c < 16; c++) o[c] *= corr;
        __syncwarp();
        #pragma unroll
        for (int k = 0; k < 32; k++) {
            float p = Ps[r][k];
            #pragma unroll
            for (int c = 0; c < 16; c += 4) {
                float4 v4 = *(const float4*)&Vs[k][g*16+c];
                o[c] += p*v4.x; o[c+1] += p*v4.y; o[c+2] += p*v4.z; o[c+3] += p*v4.w;
            }
        }
        __syncthreads();
    }
    float inv = 1.f / l;
    int sg = qt*64 + r;
    #pragma unroll
    for (int c = 0; c < 16; c++)
        g_attn[(size_t)sg*D + h*HD + g*16 + c] = o[c] * inv;
}

// ----------------------------- router + top-3 --------------------------------
__global__ void k_router(const float* __restrict__ rw, const float* __restrict__ rb) {
    int s = blockIdx.x, tid = threadIdx.x;
    float part[E];
    #pragma unroll
    for (int e = 0; e < E; e++) part[e] = 0.f;
    for (int d = tid; d < D; d += 256) {
        float xv = g_xn2[(size_t)s*D + d];
        const float* wr = rw + (size_t)d*E;
        #pragma unroll
        for (int e = 0; e < E; e++) part[e] += xv * wr[e];
    }
    __shared__ float red[256];
    __shared__ float logit[E];
    for (int e = 0; e < E; e++) {
        red[tid] = part[e]; __syncthreads();
        for (int st = 128; st > 0; st >>= 1) { if (tid < st) red[tid] += red[tid+st]; __syncthreads(); }
        if (tid == 0) logit[e] = red[0] + rb[e];
        __syncthreads();
    }
    if (tid == 0) {
        float sq = 0.f, sg[E];
        #pragma unroll
        for (int e = 0; e < E; e++) { sq += logit[e]*logit[e]; sg[e] = 1.f/(1.f + expf(-logit[e])); }
        atomicAdd(&g_aux[0], sq);
        bool used[E]; 
        #pragma unroll
        for (int e = 0; e < E; e++) used[e] = false;
        int idx[NACT]; float val[NACT];
        for (int k = 0; k < NACT; k++) {
            float best = -1e30f; int bi = 0;
            for (int e = 0; e < E; e++) if (!used[e] && sg[e] > best) { best = sg[e]; bi = e; }
            used[bi] = true; idx[k] = bi; val[k] = best;
        }
        float sum = val[0] + val[1] + val[2] + 1e-6f;
        for (int k = 0; k < NACT; k++) {
            g_topi[s*NACT + k] = idx[k];
            g_topw[s*NACT + k] = val[k] / sum;
            atomicAdd(&g_counts[idx[k]], 1);
        }
    }
}

__global__ void k_offsets() {
    if (threadIdx.x == 0) {
        int a = 0;
        for (int e = 0; e < E; e++) { g_offsets[e] = a; g_cursor[e] = a; a += g_counts[e]; }
        g_offsets[E] = a;
    }
}

__global__ void k_fill() {
    int s = blockIdx.x*256 + threadIdx.x;
    if (s >= S) return;
    for (int k = 0; k < NACT; k++) {
        int e = g_topi[s*NACT + k];
        int pos = atomicAdd(&g_cursor[e], 1);
        g_rowmap[pos] = s;
        g_slotscale[pos] = g_topw[s*NACT + k];
        g_slotpos[s*NACT + k] = pos;
    }
}

// ----------------------------- SwiGLU ----------------------------------------
__global__ void k_swiglu() {
    size_t i = (size_t)blockIdx.x*256 + threadIdx.x;   // NSLOT*HID total
    size_t row = i >> 12, col = i & (HID-1);
    float h1 = g_h[row*(2*HID) + col];
    float h2 = g_h[row*(2*HID) + HID + col];
    g_g[i] = h1 / (1.f + __expf(-h1)) * h2;
}

// ----------------------------- final combine ---------------------------------
__global__ void k_final(float* __restrict__ out) {
    size_t i = (size_t)blockIdx.x*256 + threadIdx.x;   // S*D
    int s = (int)(i >> 10);
    int d = (int)(i & (D-1));
    float v = g_xmid[i];
    #pragma unroll
    for (int k = 0; k < NACT; k++) {
        int pos = g_slotpos[s*NACT + k];
        v += g_oslot[(size_t)pos*D + d];
    }
    out[i] = v;
}

__global__ void k_aux(float* out) {
    out[(size_t)S*D] = 0.01f * g_aux[0] / (float)(S*E);
}

// ----------------------------- launch ----------------------------------------
extern "C" void kernel_launch(void* const* d_in, const int* in_sizes, int n_in,
                              void* d_out, int out_size) {
    const float* x        = (const float*)d_in[0];
    const float* rope_pos = (const float*)d_in[1];
    const float* inv_freq = (const float*)d_in[2];
    const float* qkv_w    = (const float*)d_in[3];
    const float* hh_vs    = (const float*)d_in[4];
    const float* out_w    = (const float*)d_in[5];
    const float* gate_w   = (const float*)d_in[6];
    const float* gate_b   = (const float*)d_in[7];
    const float* router_w = (const float*)d_in[8];
    const float* router_b = (const float*)d_in[9];
    const float* w12      = (const float*)d_in[10];
    const float* w3       = (const float*)d_in[11];
    float* out = (float*)d_out;

    float *p_xn, *p_qkv, *p_attn, *p_attnP, *p_xmid, *p_xn2, *p_h, *p_g, *p_oslot;
    cudaGetSymbolAddress((void**)&p_xn,    g_xn);
    cudaGetSymbolAddress((void**)&p_qkv,   g_qkv);
    cudaGetSymbolAddress((void**)&p_attn,  g_attn);
    cudaGetSymbolAddress((void**)&p_attnP, g_attnP);
    cudaGetSymbolAddress((void**)&p_xmid,  g_xmid);
    cudaGetSymbolAddress((void**)&p_xn2,   g_xn2);
    cudaGetSymbolAddress((void**)&p_h,     g_h);
    cudaGetSymbolAddress((void**)&p_g,     g_g);
    cudaGetSymbolAddress((void**)&p_oslot, g_oslot);

    k_reset<<<1, 32>>>();
    k_rmsnorm<<<S, 256>>>(x, p_xn);
    // qkv: [2048,1024] @ [1024,3072]
    k_sgemm<0><<<dim3(3*D/128, S/128), 256>>>(p_xn, qkv_w, p_qkv, S, 3*D, D, nullptr, nullptr);
    k_house<<<1, 256>>>(hh_vs);
    k_rope<<<S, 256>>>(rope_pos, inv_freq);
    k_attn<<<dim3(S/64, HEADS), 256>>>();
    // out proj
    k_sgemm<0><<<dim3(D/128, S/128), 256>>>(p_attn, out_w, p_attnP, S, D, D, nullptr, nullptr);
    // gate + residual fused epilogue: xmid = x + attnP * sigmoid(attnP@gate_w + b)
    k_sgemm<1><<<dim3(D/128, S/128), 256>>>(p_attnP, gate_w, p_xmid, S, D, D, x, gate_b);
    k_rmsnorm<<<S, 256>>>(p_xmid, p_xn2);
    k_router<<<S, 256>>>(router_w, router_b);
    k_offsets<<<1, 32>>>();
    k_fill<<<(S + 255)/256, 256>>>();
    // MoE stage 1: h = xn2[gathered] @ w12[e]   (M=6144 grouped, N=8192, K=1024)
    k_sgemm_group<true, false><<<dim3(2*HID/128, E*TPE), 256>>>(p_xn2, w12, p_h, 2*HID, D, (long long)D*2*HID);
    k_swiglu<<<(int)((size_t)NSLOT*HID/256), 256>>>();
    // MoE stage 2: oslot = (g @ w3[e]) * slot_weight   (N=1024, K=4096)
    k_sgemm_group<false, true><<<dim3(D/128, E*TPE), 256>>>(p_g, w3, p_oslot, D, HID, (long long)HID*D);
    k_final<<<(int)((size_t)S*D/256), 256>>>(out);
    if (out_size > S*D) k_aux<<<1, 1>>>(out);
}

// round 5
// speedup vs baseline: 1.6049x; 1.6049x over previous
#include <cuda_runtime.h>
#include <cuda_bf16.h>
#include <math.h>
#include <stdint.h>

// ----------------------------- constants ------------------------------------
#define S     2048
#define D     1024
#define HEADS 16
#define HD    64
#define E     8
#define HID   4096
#define NACT  3
#define NSLOT (S*NACT)          // 6144
#define TPE   16                // max 128-row tiles per expert

#define KCH   64                // K per chunk (bf16 elems) = 128B rows
#define STAGE_BYTES 65536       // 4 tiles (Ah,Al,Bh,Bl) x 16KB
#define SMEM_GEMM (3*STAGE_BYTES)

// ----------------------------- scratch (device globals) ---------------------
__device__ float g_xn   [S*D];
__device__ float g_qkv  [S*3*D];
__device__ float g_qr   [HEADS*S*HD];
__device__ float g_kr   [HEADS*S*HD];
__device__ float g_attn [S*D];
__device__ float g_attnP[S*D];
__device__ float g_xmid [S*D];
__device__ float g_xn2  [S*D];
__device__ float g_Q    [HD*HD];
__device__ float g_h    [(size_t)NSLOT*2*HID];
__device__ float g_oslot[(size_t)NSLOT*D];
__device__ int   g_counts[E];
__device__ int   g_offsets[E+1];
__device__ int   g_cursor[E];
__device__ int   g_rowmap[NSLOT];
__device__ float g_slotscale[NSLOT];
__device__ int   g_slotpos[NSLOT];
__device__ int   g_topi[S*NACT];
__device__ float g_topw[S*NACT];
__device__ float g_aux[1];

// bf16 hi/lo split buffers
__device__ __nv_bfloat16 g_w12t_h[(size_t)E*2*HID*D];
__device__ __nv_bfloat16 g_w12t_l[(size_t)E*2*HID*D];
__device__ __nv_bfloat16 g_w3t_h [(size_t)E*D*HID];
__device__ __nv_bfloat16 g_w3t_l [(size_t)E*D*HID];
__device__ __nv_bfloat16 g_qkvt_h[3*D*D];
__device__ __nv_bfloat16 g_qkvt_l[3*D*D];
__device__ __nv_bfloat16 g_outt_h[D*D];
__device__ __nv_bfloat16 g_outt_l[D*D];
__device__ __nv_bfloat16 g_gatet_h[D*D];
__device__ __nv_bfloat16 g_gatet_l[D*D];
__device__ __nv_bfloat16 g_xn_h[S*D],   g_xn_l[S*D];
__device__ __nv_bfloat16 g_attn_h[S*D], g_attn_l[S*D];
__device__ __nv_bfloat16 g_attnP_h[S*D],g_attnP_l[S*D];
__device__ __nv_bfloat16 g_xn2_h[S*D],  g_xn2_l[S*D];
__device__ __nv_bfloat16 g_gh[(size_t)NSLOT*HID], g_gl[(size_t)NSLOT*HID];

// ----------------------------- PTX helpers ----------------------------------
__device__ __forceinline__ uint32_t smem_u32(const void* p) {
    uint32_t a;
    asm("{ .reg .u64 t; cvta.to.shared.u64 t, %1; cvt.u32.u64 %0, t; }" : "=r"(a) : "l"(p));
    return a;
}
#define CP_ASYNC16(sm, gm) \
    asm volatile("cp.async.cg.shared.global [%0], [%1], 16;" :: "r"(sm), "l"(gm))
#define CP_COMMIT() asm volatile("cp.async.commit_group;" ::: "memory")
#define CP_WAIT2()  asm volatile("cp.async.wait_group 2;" ::: "memory")

__device__ __forceinline__ void ldsm4(uint32_t* r, uint32_t addr) {
    asm volatile("ldmatrix.sync.aligned.m8n8.x4.shared.b16 {%0,%1,%2,%3}, [%4];"
        : "=r"(r[0]), "=r"(r[1]), "=r"(r[2]), "=r"(r[3]) : "r"(addr));
}
__device__ __forceinline__ void mma_bf16(float* d, const uint32_t* a, const uint32_t* b) {
    asm volatile(
        "mma.sync.aligned.m16n8k16.row.col.f32.bf16.bf16.f32 "
        "{%0,%1,%2,%3}, {%4,%5,%6,%7}, {%8,%9}, {%0,%1,%2,%3};"
        : "+f"(d[0]), "+f"(d[1]), "+f"(d[2]), "+f"(d[3])
        : "r"(a[0]), "r"(a[1]), "r"(a[2]), "r"(a[3]), "r"(b[0]), "r"(b[1]));
}

// ----------------------------- small kernels --------------------------------
__global__ void k_reset() {
    int t = threadIdx.x;
    if (t < E) g_counts[t] = 0;
    if (t == 0) g_aux[0] = 0.f;
}

__global__ void k_rmsnorm(const float* __restrict__ x, float* __restrict__ o) {
    int s = blockIdx.x;
    __shared__ float red[256];
    float ss = 0.f;
    for (int d = threadIdx.x; d < D; d += 256) { float v = x[(size_t)s*D+d]; ss += v*v; }
    red[threadIdx.x] = ss; __syncthreads();
    for (int st = 128; st > 0; st >>= 1) { if (threadIdx.x < st) red[threadIdx.x] += red[threadIdx.x+st]; __syncthreads(); }
    float r = rsqrtf(red[0] * (1.f/D) + 1e-6f);
    for (int d = threadIdx.x; d < D; d += 256) o[(size_t)s*D+d] = x[(size_t)s*D+d]*r;
}

// split fp32 -> bf16 hi/lo
__global__ void k_cvt(const float* __restrict__ in, __nv_bfloat16* __restrict__ h,
                      __nv_bfloat16* __restrict__ l, size_t n) {
    size_t i = (size_t)blockIdx.x*256 + threadIdx.x;
    if (i >= n) return;
    float v = in[i];
    __nv_bfloat16 hh = __float2bfloat16(v);
    h[i] = hh;
    l[i] = __float2bfloat16(v - __bfloat162float(hh));
}

// transpose [K,N] fp32 -> [N,K] bf16 hi/lo (blockIdx.z = expert)
__global__ void k_cvt_t(const float* __restrict__ in, __nv_bfloat16* __restrict__ h,
                        __nv_bfloat16* __restrict__ l, int K, int N) {
    __shared__ float t[32][33];
    const float* inp = in + (size_t)blockIdx.z*K*N;
    __nv_bfloat16* hp = h + (size_t)blockIdx.z*K*N;
    __nv_bfloat16* lp = l + (size_t)blockIdx.z*K*N;
    int n0 = blockIdx.x*32, k0 = blockIdx.y*32;
    for (int r = threadIdx.y; r < 32; r += 8)
        t[r][threadIdx.x] = inp[(size_t)(k0+r)*N + n0 + threadIdx.x];
    __syncthreads();
    for (int r = threadIdx.y; r < 32; r += 8) {
        float v = t[threadIdx.x][r];
        __nv_bfloat16 hh = __float2bfloat16(v);
        size_t o = (size_t)(n0+r)*K + k0 + threadIdx.x;
        hp[o] = hh;
        lp[o] = __float2bfloat16(v - __bfloat162float(hh));
    }
}

// ----------------------------- tensor-core GEMM ------------------------------
// C[M,N] = A[M,K] @ Bt[N,K]^T via bf16x3 emulation (AhBh + AlBh + AhBl), fp32 acc.
// MODE 0: dense, plain store
// MODE 1: dense, gate epilogue: C = resid + Aelem*sigmoid(acc + bias[col])
// MODE 2: grouped (g_offsets), gather A rows via g_rowmap, store per slot
// MODE 3: grouped, identity rows, store scaled by g_slotscale
// Tile: CTA 128x128, 8 warps (4m x 2n), warp 32x64, Kc=64, 3-stage cp.async.
// smem stage layout: Ah@0, Al@16K, Bh@32K, Bl@48K; rows 128B, chunk^= (row&7).
template<int MODE>
__global__ void __launch_bounds__(256, 1) k_gemm_mma(
    const __nv_bfloat16* __restrict__ Ah, const __nv_bfloat16* __restrict__ Al,
    const __nv_bfloat16* __restrict__ Bh, const __nv_bfloat16* __restrict__ Bl,
    float* __restrict__ C, int N, int K,
    const float* __restrict__ Aelem, const float* __restrict__ resid,
    const float* __restrict__ bias, long long ldbE)
{
    extern __shared__ char smem[];
    __shared__ int ridx[128];
    int tid = threadIdx.x, wid = tid >> 5, lane = tid & 31;
    int col0 = blockIdx.x * 128;
    int row0, rows;
    if (MODE >= 2) {
        int e = blockIdx.y / TPE, t = blockIdx.y % TPE;
        int start = g_offsets[e], end = g_offsets[e+1];
        row0 = start + t * 128;
        if (row0 >= end) return;
        rows = end - row0; if (rows > 128) rows = 128;
        Bh += (size_t)e * ldbE; Bl += (size_t)e * ldbE;
        if (tid < 128) {
            int rr = tid < rows ? tid : rows - 1;
            ridx[tid] = (MODE == 2) ? g_rowmap[row0 + rr] : (row0 + rr);
        }
        __syncthreads();
    } else { row0 = blockIdx.y * 128; rows = 128; }

    uint32_t sbase = smem_u32(smem);
    const int nch = K / KCH;

    // -------- async tile loader --------
    auto issue = [&](int stg, int ch) {
        uint32_t stoff = sbase + (uint32_t)stg * STAGE_BYTES;
        int kk = ch * KCH;
        #pragma unroll
        for (int t = 0; t < 4; t++) {
            const __nv_bfloat16* src = (t == 0) ? Ah : (t == 1) ? Al : (t == 2) ? Bh : Bl;
            #pragma unroll
            for (int i = 0; i < 4; i++) {
                int idx = i * 256 + tid;          // 0..1023
                int r = idx >> 3, seg = idx & 7;
                uint32_t so = stoff + (uint32_t)t * 16384u
                            + (uint32_t)(r * 128 + ((seg ^ (r & 7)) * 16));
                int grow = (t < 2) ? ((MODE >= 2) ? ridx[r] : row0 + r) : (col0 + r);
                const void* gp = src + (size_t)grow * K + kk + seg * 8;
                CP_ASYNC16(so, gp);
            }
        }
    };

    float d[2][8][4] = {};
    int m0w = (wid & 3) * 32, n0w = (wid >> 2) * 64;

    issue(0, 0); CP_COMMIT();
    issue(1, 1); CP_COMMIT();

    for (int c = 0; c < nch; c++) {
        __syncthreads();                      // buffer (c+2)%3 free to overwrite
        if (c + 2 < nch) issue((c + 2) % 3, c + 2);
        CP_COMMIT();
        CP_WAIT2();                           // stage c's group complete
        __syncthreads();
        uint32_t st = sbase + (uint32_t)(c % 3) * STAGE_BYTES;
        #pragma unroll
        for (int ks = 0; ks < 4; ks++) {      // k16 steps within Kc=64
            uint32_t ah[2][4], al[2][4], bh[8][2], bl[8][2];
            #pragma unroll
            for (int mt = 0; mt < 2; mt++) {
                int row = m0w + mt * 16 + (lane & 15);
                int ch2 = ks * 2 + (lane >> 4);
                uint32_t ad = st + (uint32_t)(row * 128 + ((ch2 ^ (row & 7)) * 16));
                ldsm4(ah[mt], ad);
                ldsm4(al[mt], ad + 16384u);
            }
            #pragma unroll
            for (int nt = 0; nt < 4; nt++) {
                int row = n0w + nt * 16 + ((lane >> 4) & 1) * 8 + (lane & 7);
                int ch2 = ks * 2 + ((lane >> 3) & 1);
                uint32_t bd = st + 32768u + (uint32_t)(row * 128 + ((ch2 ^ (row & 7)) * 16));
                uint32_t tmp[4];
                ldsm4(tmp, bd);
                bh[nt*2][0] = tmp[0]; bh[nt*2][1] = tmp[1];
                bh[nt*2+1][0] = tmp[2]; bh[nt*2+1][1] = tmp[3];
                ldsm4(tmp, bd + 16384u);
                bl[nt*2][0] = tmp[0]; bl[nt*2][1] = tmp[1];
                bl[nt*2+1][0] = tmp[2]; bl[nt*2+1][1] = tmp[3];
            }
            #pragma unroll
            for (int mt = 0; mt < 2; mt++)
                #pragma unroll
                for (int nt = 0; nt < 8; nt++) {
                    mma_bf16(d[mt][nt], ah[mt], bh[nt]);
                    mma_bf16(d[mt][nt], al[mt], bh[nt]);
                    mma_bf16(d[mt][nt], ah[mt], bl[nt]);
                }
        }
    }

    // -------- epilogue --------
    int grp = lane >> 2, qd = lane & 3;
    #pragma unroll
    for (int mt = 0; mt < 2; mt++) {
        #pragma unroll
        for (int half = 0; half < 2; half++) {
            int rr = m0w + mt * 16 + grp + half * 8;
            if (MODE >= 2 && rr >= rows) continue;
            int r = row0 + rr;
            float sc = (MODE == 3) ? g_slotscale[r] : 1.f;
            #pragma unroll
            for (int nt = 0; nt < 8; nt++) {
                #pragma unroll
                for (int e2 = 0; e2 < 2; e2++) {
                    int col = col0 + n0w + nt * 8 + qd * 2 + e2;
                    float v = d[mt][nt][half * 2 + e2];
                    if (MODE == 1) {
                        float gt = 1.f / (1.f + __expf(-(v + bias[col])));
                        v = resid[(size_t)r*N + col] + Aelem[(size_t)r*N + col] * gt;
                    } else if (MODE == 3) v *= sc;
                    C[(size_t)r*N + col] = v;
                }
            }
        }
    }
}

// ----------------------------- Householder Q --------------------------------
__global__ void k_house(const float* __restrict__ vs) {
    __shared__ float Q[64][65];
    __shared__ float v[64], w[64];
    __shared__ float vn;
    int tid = threadIdx.x;
    for (int i = tid; i < 4096; i += 256) Q[i>>6][i&63] = ((i>>6)==(i&63)) ? 1.f : 0.f;
    __syncthreads();
    for (int r = 0; r < 32; r++) {
        if (tid < 64) v[tid] = vs[r*64 + tid];
        __syncthreads();
        if (tid == 0) { float s = 0.f; for (int i = 0; i < 64; i++) s += v[i]*v[i]; vn = 2.f / (s + 1e-8f); }
        if (tid < 64) { float s = 0.f; for (int i = 0; i < 64; i++) s += v[i]*Q[i][tid]; w[tid] = s; }
        __syncthreads();
        for (int i = tid; i < 4096; i += 256) { int a = i>>6, b = i&63; Q[a][b] -= vn * v[a] * w[b]; }
        __syncthreads();
    }
    for (int i = tid; i < 4096; i += 256) g_Q[i] = Q[i>>6][i&63];
}

// ----------------------------- RnRoPE ----------------------------------------
__global__ void __launch_bounds__(256) k_rope(const float* __restrict__ rope_pos,
                                              const float* __restrict__ inv_freq) {
    int s = blockIdx.x;
    __shared__ float Q[64][65];
    __shared__ float cs[32], sn[32];
    __shared__ float vec[4][64], tv[4][64];
    int tid = threadIdx.x;
    for (int i = tid; i < 4096; i += 256) Q[i>>6][i&63] = g_Q[i];
    if (tid < 32) {
        float f = 0.f;
        if (tid < 15) f = rope_pos[s*3 + tid/5] * inv_freq[tid % 5];
        cs[tid] = cosf(f); sn[tid] = sinf(f);
    }
    __syncthreads();
    int grp = tid >> 6, lane = tid & 63;
    for (int vb = 0; vb < 32; vb += 4) {
        int vi = vb + grp;
        int h = vi >> 1, isk = vi & 1;
        const float* src = g_qkv + (size_t)s*3*D + isk*D + h*HD;
        vec[grp][lane] = src[lane];
        __syncthreads();
        float t0 = 0.f, t1 = 0.f;
        #pragma unroll
        for (int d = 0; d < 64; d += 2) { t0 += vec[grp][d]*Q[lane][d]; t1 += vec[grp][d+1]*Q[lane][d+1]; }
        tv[grp][lane] = t0 + t1;
        __syncthreads();
        int p = lane & 31;
        float c = cs[p], si = sn[p];
        float rr = (lane < 32) ? (tv[grp][lane]*c - tv[grp][lane+32]*si)
                               : (tv[grp][lane]*c + tv[grp][lane-32]*si);
        __syncthreads();
        vec[grp][lane] = rr;
        __syncthreads();
        float o0 = 0.f, o1 = 0.f;
        #pragma unroll
        for (int d = 0; d < 64; d += 2) { o0 += vec[grp][d]*Q[d][lane]; o1 += vec[grp][d+1]*Q[d+1][lane]; }
        float* dst = (isk ? g_kr : g_qr) + ((size_t)h*S + s)*HD;
        dst[lane] = o0 + o1;
        __syncthreads();
    }
}

// ----------------------------- flash attention -------------------------------
__global__ void __launch_bounds__(256) k_attn() {
    int qt = blockIdx.x, h = blockIdx.y;
    __shared__ float Ks[32][68];
    __shared__ float Vs[32][68];
    __shared__ float Ps[64][33];
    int tid = threadIdx.x, r = tid >> 2, g = tid & 3;

    float qreg[64];
    const float* qrow = g_qr + ((size_t)h*S + qt*64 + r)*HD;
    #pragma unroll
    for (int d = 0; d < 64; d += 4) {
        float4 q4 = *(const float4*)(qrow + d);
        qreg[d] = q4.x; qreg[d+1] = q4.y; qreg[d+2] = q4.z; qreg[d+3] = q4.w;
    }
    float m = -1e30f, l = 0.f, o[16];
    #pragma unroll
    for (int c = 0; c < 16; c++) o[c] = 0.f;

    for (int kt = 0; kt < S; kt += 32) {
        for (int i = tid; i < 32*64; i += 256) {
            int kr = i >> 6, kd = i & 63;
            Ks[kr][kd] = g_kr[((size_t)h*S + kt + kr)*HD + kd];
            Vs[kr][kd] = g_qkv[(size_t)(kt+kr)*3*D + 2*D + h*HD + kd];
        }
        __syncthreads();
        float sc[8];
        #pragma unroll
        for (int kk = 0; kk < 8; kk++) sc[kk] = 0.f;
        #pragma unroll
        for (int d = 0; d < 64; d += 4) {
            #pragma unroll
            for (int kk = 0; kk < 8; kk++) {
                int k = g*8 + kk;
                float4 k4 = *(const float4*)&Ks[k][d];
                sc[kk] += qreg[d]*k4.x + qreg[d+1]*k4.y + qreg[d+2]*k4.z + qreg[d+3]*k4.w;
            }
        }
        float mx = -1e30f;
        #pragma unroll
        for (int kk = 0; kk < 8; kk++) { sc[kk] *= 0.125f; mx = fmaxf(mx, sc[kk]); }
        mx = fmaxf(mx, __shfl_xor_sync(0xffffffffu, mx, 1));
        mx = fmaxf(mx, __shfl_xor_sync(0xffffffffu, mx, 2));
        float mnew = fmaxf(m, mx);
        float corr = __expf(m - mnew);
        float ps = 0.f;
        #pragma unroll
        for (int kk = 0; kk < 8; kk++) {
            float p = __expf(sc[kk] - mnew);
            Ps[r][g*8+kk] = p; ps += p;
        }
        ps += __shfl_xor_sync(0xffffffffu, ps, 1);
        ps += __shfl_xor_sync(0xffffffffu, ps, 2);
        l = l*corr + ps; m = mnew;
        #pragma unroll
        for (int c = 0; c < 16; c++) o[c] *= corr;
        __syncwarp();
        #pragma unroll
        for (int k = 0; k < 32; k++) {
            float p = Ps[r][k];
            #pragma unroll
            for (int c = 0; c < 16; c += 4) {
                float4 v4 = *(const float4*)&Vs[k][g*16+c];
                o[c] += p*v4.x; o[c+1] += p*v4.y; o[c+2] += p*v4.z; o[c+3] += p*v4.w;
            }
        }
        __syncthreads();
    }
    float inv = 1.f / l;
    int sg = qt*64 + r;
    #pragma unroll
    for (int c = 0; c < 16; c++)
        g_attn[(size_t)sg*D + h*HD + g*16 + c] = o[c] * inv;
}

// ----------------------------- router + top-3 --------------------------------
__global__ void k_router(const float* __restrict__ rw, const float* __restrict__ rb) {
    int s = blockIdx.x, tid = threadIdx.x;
    float part[E];
    #pragma unroll
    for (int e = 0; e < E; e++) part[e] = 0.f;
    for (int d = tid; d < D; d += 256) {
        float xv = g_xn2[(size_t)s*D + d];
        const float* wr = rw + (size_t)d*E;
        #pragma unroll
        for (int e = 0; e < E; e++) part[e] += xv * wr[e];
    }
    __shared__ float red[256];
    __shared__ float logit[E];
    for (int e = 0; e < E; e++) {
        red[tid] = part[e]; __syncthreads();
        for (int st = 128; st > 0; st >>= 1) { if (tid < st) red[tid] += red[tid+st]; __syncthreads(); }
        if (tid == 0) logit[e] = red[0] + rb[e];
        __syncthreads();
    }
    if (tid == 0) {
        float sq = 0.f, sg[E];
        #pragma unroll
        for (int e = 0; e < E; e++) { sq += logit[e]*logit[e]; sg[e] = 1.f/(1.f + expf(-logit[e])); }
        atomicAdd(&g_aux[0], sq);
        bool used[E];
        #pragma unroll
        for (int e = 0; e < E; e++) used[e] = false;
        int idx[NACT]; float val[NACT];
        for (int k = 0; k < NACT; k++) {
            float best = -1e30f; int bi = 0;
            for (int e = 0; e < E; e++) if (!used[e] && sg[e] > best) { best = sg[e]; bi = e; }
            used[bi] = true; idx[k] = bi; val[k] = best;
        }
        float sum = val[0] + val[1] + val[2] + 1e-6f;
        for (int k = 0; k < NACT; k++) {
            g_topi[s*NACT + k] = idx[k];
            g_topw[s*NACT + k] = val[k] / sum;
            atomicAdd(&g_counts[idx[k]], 1);
        }
    }
}

__global__ void k_offsets() {
    if (threadIdx.x == 0) {
        int a = 0;
        for (int e = 0; e < E; e++) { g_offsets[e] = a; g_cursor[e] = a; a += g_counts[e]; }
        g_offsets[E] = a;
    }
}

__global__ void k_fill() {
    int s = blockIdx.x*256 + threadIdx.x;
    if (s >= S) return;
    for (int k = 0; k < NACT; k++) {
        int e = g_topi[s*NACT + k];
        int pos = atomicAdd(&g_cursor[e], 1);
        g_rowmap[pos] = s;
        g_slotscale[pos] = g_topw[s*NACT + k];
        g_slotpos[s*NACT + k] = pos;
    }
}

// ----------------------------- SwiGLU (writes bf16 hi/lo) --------------------
__global__ void k_swiglu() {
    size_t i = (size_t)blockIdx.x*256 + threadIdx.x;   // NSLOT*HID total
    size_t row = i >> 12, col = i & (HID-1);
    float h1 = g_h[row*(2*HID) + col];
    float h2 = g_h[row*(2*HID) + HID + col];
    float v = h1 / (1.f + __expf(-h1)) * h2;
    __nv_bfloat16 hh = __float2bfloat16(v);
    g_gh[i] = hh;
    g_gl[i] = __float2bfloat16(v - __bfloat162float(hh));
}

// ----------------------------- final combine ---------------------------------
__global__ void k_final(float* __restrict__ out) {
    size_t i = (size_t)blockIdx.x*256 + threadIdx.x;   // S*D
    int s = (int)(i >> 10);
    int d = (int)(i & (D-1));
    float v = g_xmid[i];
    #pragma unroll
    for (int k = 0; k < NACT; k++) {
        int pos = g_slotpos[s*NACT + k];
        v += g_oslot[(size_t)pos*D + d];
    }
    out[i] = v;
}

__global__ void k_aux(float* out) {
    out[(size_t)S*D] = 0.01f * g_aux[0] / (float)(S*E);
}

// ----------------------------- launch ----------------------------------------
extern "C" void kernel_launch(void* const* d_in, const int* in_sizes, int n_in,
                              void* d_out, int out_size) {
    const float* x        = (const float*)d_in[0];
    const float* rope_pos = (const float*)d_in[1];
    const float* inv_freq = (const float*)d_in[2];
    const float* qkv_w    = (const float*)d_in[3];
    const float* hh_vs    = (const float*)d_in[4];
    const float* out_w    = (const float*)d_in[5];
    const float* gate_w   = (const float*)d_in[6];
    const float* gate_b   = (const float*)d_in[7];
    const float* router_w = (const float*)d_in[8];
    const float* router_b = (const float*)d_in[9];
    const float* w12      = (const float*)d_in[10];
    const float* w3       = (const float*)d_in[11];
    float* out = (float*)d_out;

    cudaFuncSetAttribute(k_gemm_mma<0>, cudaFuncAttributeMaxDynamicSharedMemorySize, SMEM_GEMM);
    cudaFuncSetAttribute(k_gemm_mma<1>, cudaFuncAttributeMaxDynamicSharedMemorySize, SMEM_GEMM);
    cudaFuncSetAttribute(k_gemm_mma<2>, cudaFuncAttributeMaxDynamicSharedMemorySize, SMEM_GEMM);
    cudaFuncSetAttribute(k_gemm_mma<3>, cudaFuncAttributeMaxDynamicSharedMemorySize, SMEM_GEMM);

    float *p_xn, *p_qkv, *p_attn, *p_attnP, *p_xmid, *p_xn2, *p_h, *p_oslot;
    cudaGetSymbolAddress((void**)&p_xn,    g_xn);
    cudaGetSymbolAddress((void**)&p_qkv,   g_qkv);
    cudaGetSymbolAddress((void**)&p_attn,  g_attn);
    cudaGetSymbolAddress((void**)&p_attnP, g_attnP);
    cudaGetSymbolAddress((void**)&p_xmid,  g_xmid);
    cudaGetSymbolAddress((void**)&p_xn2,   g_xn2);
    cudaGetSymbolAddress((void**)&p_h,     g_h);
    cudaGetSymbolAddress((void**)&p_oslot, g_oslot);
    __nv_bfloat16 *b_w12h,*b_w12l,*b_w3h,*b_w3l,*b_qkvh,*b_qkvl,*b_outh,*b_outl,*b_gateh,*b_gatel;
    __nv_bfloat16 *b_xnh,*b_xnl,*b_attnh,*b_attnl,*b_aph,*b_apl,*b_xn2h,*b_xn2l,*b_gh,*b_gl;
    cudaGetSymbolAddress((void**)&b_w12h, g_w12t_h);  cudaGetSymbolAddress((void**)&b_w12l, g_w12t_l);
    cudaGetSymbolAddress((void**)&b_w3h,  g_w3t_h);   cudaGetSymbolAddress((void**)&b_w3l,  g_w3t_l);
    cudaGetSymbolAddress((void**)&b_qkvh, g_qkvt_h);  cudaGetSymbolAddress((void**)&b_qkvl, g_qkvt_l);
    cudaGetSymbolAddress((void**)&b_outh, g_outt_h);  cudaGetSymbolAddress((void**)&b_outl, g_outt_l);
    cudaGetSymbolAddress((void**)&b_gateh,g_gatet_h); cudaGetSymbolAddress((void**)&b_gatel,g_gatet_l);
    cudaGetSymbolAddress((void**)&b_xnh,  g_xn_h);    cudaGetSymbolAddress((void**)&b_xnl,  g_xn_l);
    cudaGetSymbolAddress((void**)&b_attnh,g_attn_h);  cudaGetSymbolAddress((void**)&b_attnl,g_attn_l);
    cudaGetSymbolAddress((void**)&b_aph,  g_attnP_h); cudaGetSymbolAddress((void**)&b_apl,  g_attnP_l);
    cudaGetSymbolAddress((void**)&b_xn2h, g_xn2_h);   cudaGetSymbolAddress((void**)&b_xn2l, g_xn2_l);
    cudaGetSymbolAddress((void**)&b_gh,   g_gh);      cudaGetSymbolAddress((void**)&b_gl,   g_gl);

    k_reset<<<1, 32>>>();
    // weight conversions (transpose + bf16 split)
    k_cvt_t<<<dim3(3*D/32, D/32, 1), dim3(32,8)>>>(qkv_w,  b_qkvh,  b_qkvl,  D, 3*D);
    k_cvt_t<<<dim3(D/32,   D/32, 1), dim3(32,8)>>>(out_w,  b_outh,  b_outl,  D, D);
    k_cvt_t<<<dim3(D/32,   D/32, 1), dim3(32,8)>>>(gate_w, b_gateh, b_gatel, D, D);
    k_cvt_t<<<dim3(2*HID/32, D/32, E), dim3(32,8)>>>(w12, b_w12h, b_w12l, D, 2*HID);
    k_cvt_t<<<dim3(D/32, HID/32,  E), dim3(32,8)>>>(w3,  b_w3h,  b_w3l,  HID, D);

    k_rmsnorm<<<S, 256>>>(x, p_xn);
    k_cvt<<<(S*D+255)/256, 256>>>(p_xn, b_xnh, b_xnl, (size_t)S*D);
    // qkv: [2048,1024] x [1024,3072]
    k_gemm_mma<0><<<dim3(3*D/128, S/128), 256, SMEM_GEMM>>>(b_xnh, b_xnl, b_qkvh, b_qkvl,
        p_qkv, 3*D, D, nullptr, nullptr, nullptr, 0);
    k_house<<<1, 256>>>(hh_vs);
    k_rope<<<S, 256>>>(rope_pos, inv_freq);
    k_attn<<<dim3(S/64, HEADS), 256>>>();
    k_cvt<<<(S*D+255)/256, 256>>>(p_attn, b_attnh, b_attnl, (size_t)S*D);
    // out proj
    k_gemm_mma<0><<<dim3(D/128, S/128), 256, SMEM_GEMM>>>(b_attnh, b_attnl, b_outh, b_outl,
        p_attnP, D, D, nullptr, nullptr, nullptr, 0);
    k_cvt<<<(S*D+255)/256, 256>>>(p_attnP, b_aph, b_apl, (size_t)S*D);
    // gate + residual fused epilogue
    k_gemm_mma<1><<<dim3(D/128, S/128), 256, SMEM_GEMM>>>(b_aph, b_apl, b_gateh, b_gatel,
        p_xmid, D, D, p_attnP, x, gate_b, 0);
    k_rmsnorm<<<S, 256>>>(p_xmid, p_xn2);
    k_cvt<<<(S*D+255)/256, 256>>>(p_xn2, b_xn2h, b_xn2l, (size_t)S*D);
    k_router<<<S, 256>>>(router_w, router_b);
    k_offsets<<<1, 32>>>();
    k_fill<<<(S + 255)/256, 256>>>();
    // MoE stage 1: h = xn2[gathered] @ w12[e]   (grouped M<=6144, N=8192, K=1024)
    k_gemm_mma<2><<<dim3(2*HID/128, E*TPE), 256, SMEM_GEMM>>>(b_xn2h, b_xn2l, b_w12h, b_w12l,
        p_h, 2*HID, D, nullptr, nullptr, nullptr, (long long)2*HID*D);
    k_swiglu<<<(int)((size_t)NSLOT*HID/256), 256>>>();
    // MoE stage 2: oslot = (g @ w3[e]) * slot_weight   (N=1024, K=4096)
    k_gemm_mma<3><<<dim3(D/128, E*TPE), 256, SMEM_GEMM>>>(b_gh, b_gl, b_w3h, b_w3l,
        p_oslot, D, HID, nullptr, nullptr, nullptr, (long long)HID*D);
    k_final<<<(int)((size_t)S*D/256), 256>>>(out);
    if (out_size > S*D) k_aux<<<1, 1>>>(out);
}

// round 6
// speedup vs baseline: 1.6049x; 1.0000x over previous
#include <cuda_runtime.h>
#include <cuda_bf16.h>
#include <math.h>
#include <stdint.h>

// ----------------------------- constants ------------------------------------
#define S     2048
#define D     1024
#define HEADS 16
#define HD    64
#define E     8
#define HID   4096
#define NACT  3
#define NSLOT (S*NACT)          // 6144
#define TPE   16                // max 128-row tiles per expert

#define KCH   64                // K per chunk (bf16 elems) = 128B rows
#define STAGE_BYTES 65536       // 4 tiles (Ah,Al,Bh,Bl) x 16KB
#define SMEM_GEMM (3*STAGE_BYTES)

// ----------------------------- scratch (device globals) ---------------------
__device__ float g_xn   [S*D];
__device__ float g_qkv  [S*3*D];
__device__ float g_qr   [HEADS*S*HD];
__device__ float g_kr   [HEADS*S*HD];
__device__ float g_attn [S*D];
__device__ float g_attnP[S*D];
__device__ float g_xmid [S*D];
__device__ float g_xn2  [S*D];
__device__ float g_Q    [HD*HD];
__device__ float g_h    [(size_t)NSLOT*2*HID];
__device__ float g_oslot[(size_t)NSLOT*D];
__device__ int   g_counts[E];
__device__ int   g_offsets[E+1];
__device__ int   g_cursor[E];
__device__ int   g_rowmap[NSLOT];
__device__ float g_slotscale[NSLOT];
__device__ int   g_slotpos[NSLOT];
__device__ int   g_topi[S*NACT];
__device__ float g_topw[S*NACT];
__device__ float g_aux[1];

// bf16 hi/lo split buffers
__device__ __nv_bfloat16 g_w12t_h[(size_t)E*2*HID*D];
__device__ __nv_bfloat16 g_w12t_l[(size_t)E*2*HID*D];
__device__ __nv_bfloat16 g_w3t_h [(size_t)E*D*HID];
__device__ __nv_bfloat16 g_w3t_l [(size_t)E*D*HID];
__device__ __nv_bfloat16 g_qkvt_h[3*D*D];
__device__ __nv_bfloat16 g_qkvt_l[3*D*D];
__device__ __nv_bfloat16 g_outt_h[D*D];
__device__ __nv_bfloat16 g_outt_l[D*D];
__device__ __nv_bfloat16 g_gatet_h[D*D];
__device__ __nv_bfloat16 g_gatet_l[D*D];
__device__ __nv_bfloat16 g_xn_h[S*D],   g_xn_l[S*D];
__device__ __nv_bfloat16 g_attn_h[S*D], g_attn_l[S*D];
__device__ __nv_bfloat16 g_attnP_h[S*D],g_attnP_l[S*D];
__device__ __nv_bfloat16 g_xn2_h[S*D],  g_xn2_l[S*D];
__device__ __nv_bfloat16 g_gh[(size_t)NSLOT*HID], g_gl[(size_t)NSLOT*HID];

// ----------------------------- PTX helpers ----------------------------------
__device__ __forceinline__ uint32_t smem_u32(const void* p) {
    uint32_t a;
    asm("{ .reg .u64 t; cvta.to.shared.u64 t, %1; cvt.u32.u64 %0, t; }" : "=r"(a) : "l"(p));
    return a;
}
#define CP_ASYNC16(sm, gm) \
    asm volatile("cp.async.cg.shared.global [%0], [%1], 16;" :: "r"(sm), "l"(gm))
#define CP_COMMIT() asm volatile("cp.async.commit_group;" ::: "memory")
#define CP_WAIT2()  asm volatile("cp.async.wait_group 2;" ::: "memory")

__device__ __forceinline__ void ldsm4(uint32_t* r, uint32_t addr) {
    asm volatile("ldmatrix.sync.aligned.m8n8.x4.shared.b16 {%0,%1,%2,%3}, [%4];"
        : "=r"(r[0]), "=r"(r[1]), "=r"(r[2]), "=r"(r[3]) : "r"(addr));
}
__device__ __forceinline__ void mma_bf16(float* d, const uint32_t* a, const uint32_t* b) {
    asm volatile(
        "mma.sync.aligned.m16n8k16.row.col.f32.bf16.bf16.f32 "
        "{%0,%1,%2,%3}, {%4,%5,%6,%7}, {%8,%9}, {%0,%1,%2,%3};"
        : "+f"(d[0]), "+f"(d[1]), "+f"(d[2]), "+f"(d[3])
        : "r"(a[0]), "r"(a[1]), "r"(a[2]), "r"(a[3]), "r"(b[0]), "r"(b[1]));
}

// ----------------------------- small kernels --------------------------------
__global__ void k_reset() {
    int t = threadIdx.x;
    if (t < E) g_counts[t] = 0;
    if (t == 0) g_aux[0] = 0.f;
}

__global__ void k_rmsnorm(const float* __restrict__ x, float* __restrict__ o) {
    int s = blockIdx.x;
    __shared__ float red[256];
    float ss = 0.f;
    for (int d = threadIdx.x; d < D; d += 256) { float v = x[(size_t)s*D+d]; ss += v*v; }
    red[threadIdx.x] = ss; __syncthreads();
    for (int st = 128; st > 0; st >>= 1) { if (threadIdx.x < st) red[threadIdx.x] += red[threadIdx.x+st]; __syncthreads(); }
    float r = rsqrtf(red[0] * (1.f/D) + 1e-6f);
    for (int d = threadIdx.x; d < D; d += 256) o[(size_t)s*D+d] = x[(size_t)s*D+d]*r;
}

// split fp32 -> bf16 hi/lo
__global__ void k_cvt(const float* __restrict__ in, __nv_bfloat16* __restrict__ h,
                      __nv_bfloat16* __restrict__ l, size_t n) {
    size_t i = (size_t)blockIdx.x*256 + threadIdx.x;
    if (i >= n) return;
    float v = in[i];
    __nv_bfloat16 hh = __float2bfloat16(v);
    h[i] = hh;
    l[i] = __float2bfloat16(v - __bfloat162float(hh));
}

// transpose [K,N] fp32 -> [N,K] bf16 hi/lo (blockIdx.z = expert)
__global__ void k_cvt_t(const float* __restrict__ in, __nv_bfloat16* __restrict__ h,
                        __nv_bfloat16* __restrict__ l, int K, int N) {
    __shared__ float t[32][33];
    const float* inp = in + (size_t)blockIdx.z*K*N;
    __nv_bfloat16* hp = h + (size_t)blockIdx.z*K*N;
    __nv_bfloat16* lp = l + (size_t)blockIdx.z*K*N;
    int n0 = blockIdx.x*32, k0 = blockIdx.y*32;
    for (int r = threadIdx.y; r < 32; r += 8)
        t[r][threadIdx.x] = inp[(size_t)(k0+r)*N + n0 + threadIdx.x];
    __syncthreads();
    for (int r = threadIdx.y; r < 32; r += 8) {
        float v = t[threadIdx.x][r];
        __nv_bfloat16 hh = __float2bfloat16(v);
        size_t o = (size_t)(n0+r)*K + k0 + threadIdx.x;
        hp[o] = hh;
        lp[o] = __float2bfloat16(v - __bfloat162float(hh));
    }
}

// ----------------------------- tensor-core GEMM ------------------------------
// C[M,N] = A[M,K] @ Bt[N,K]^T via bf16x3 emulation (AhBh + AlBh + AhBl), fp32 acc.
// MODE 0: dense, plain store
// MODE 1: dense, gate epilogue: C = resid + Aelem*sigmoid(acc + bias[col])
// MODE 2: grouped (g_offsets), gather A rows via g_rowmap, store per slot
// MODE 3: grouped, identity rows, store scaled by g_slotscale
// Tile: CTA 128x128, 8 warps (4m x 2n), warp 32x64, Kc=64, 3-stage cp.async.
// smem stage layout: Ah@0, Al@16K, Bh@32K, Bl@48K; rows 128B, chunk^= (row&7).
template<int MODE>
__global__ void __launch_bounds__(256, 1) k_gemm_mma(
    const __nv_bfloat16* __restrict__ Ah, const __nv_bfloat16* __restrict__ Al,
    const __nv_bfloat16* __restrict__ Bh, const __nv_bfloat16* __restrict__ Bl,
    float* __restrict__ C, int N, int K,
    const float* __restrict__ Aelem, const float* __restrict__ resid,
    const float* __restrict__ bias, long long ldbE)
{
    extern __shared__ char smem[];
    __shared__ int ridx[128];
    int tid = threadIdx.x, wid = tid >> 5, lane = tid & 31;
    int col0 = blockIdx.x * 128;
    int row0, rows;
    if (MODE >= 2) {
        int e = blockIdx.y / TPE, t = blockIdx.y % TPE;
        int start = g_offsets[e], end = g_offsets[e+1];
        row0 = start + t * 128;
        if (row0 >= end) return;
        rows = end - row0; if (rows > 128) rows = 128;
        Bh += (size_t)e * ldbE; Bl += (size_t)e * ldbE;
        if (tid < 128) {
            int rr = tid < rows ? tid : rows - 1;
            ridx[tid] = (MODE == 2) ? g_rowmap[row0 + rr] : (row0 + rr);
        }
        __syncthreads();
    } else { row0 = blockIdx.y * 128; rows = 128; }

    uint32_t sbase = smem_u32(smem);
    const int nch = K / KCH;

    // -------- async tile loader --------
    auto issue = [&](int stg, int ch) {
        uint32_t stoff = sbase + (uint32_t)stg * STAGE_BYTES;
        int kk = ch * KCH;
        #pragma unroll
        for (int t = 0; t < 4; t++) {
            const __nv_bfloat16* src = (t == 0) ? Ah : (t == 1) ? Al : (t == 2) ? Bh : Bl;
            #pragma unroll
            for (int i = 0; i < 4; i++) {
                int idx = i * 256 + tid;          // 0..1023
                int r = idx >> 3, seg = idx & 7;
                uint32_t so = stoff + (uint32_t)t * 16384u
                            + (uint32_t)(r * 128 + ((seg ^ (r & 7)) * 16));
                int grow = (t < 2) ? ((MODE >= 2) ? ridx[r] : row0 + r) : (col0 + r);
                const void* gp = src + (size_t)grow * K + kk + seg * 8;
                CP_ASYNC16(so, gp);
            }
        }
    };

    float d[2][8][4] = {};
    int m0w = (wid & 3) * 32, n0w = (wid >> 2) * 64;

    issue(0, 0); CP_COMMIT();
    issue(1, 1); CP_COMMIT();

    for (int c = 0; c < nch; c++) {
        __syncthreads();                      // buffer (c+2)%3 free to overwrite
        if (c + 2 < nch) issue((c + 2) % 3, c + 2);
        CP_COMMIT();
        CP_WAIT2();                           // stage c's group complete
        __syncthreads();
        uint32_t st = sbase + (uint32_t)(c % 3) * STAGE_BYTES;
        #pragma unroll
        for (int ks = 0; ks < 4; ks++) {      // k16 steps within Kc=64
            uint32_t ah[2][4], al[2][4], bh[8][2], bl[8][2];
            #pragma unroll
            for (int mt = 0; mt < 2; mt++) {
                int row = m0w + mt * 16 + (lane & 15);
                int ch2 = ks * 2 + (lane >> 4);
                uint32_t ad = st + (uint32_t)(row * 128 + ((ch2 ^ (row & 7)) * 16));
                ldsm4(ah[mt], ad);
                ldsm4(al[mt], ad + 16384u);
            }
            #pragma unroll
            for (int nt = 0; nt < 4; nt++) {
                int row = n0w + nt * 16 + ((lane >> 4) & 1) * 8 + (lane & 7);
                int ch2 = ks * 2 + ((lane >> 3) & 1);
                uint32_t bd = st + 32768u + (uint32_t)(row * 128 + ((ch2 ^ (row & 7)) * 16));
                uint32_t tmp[4];
                ldsm4(tmp, bd);
                bh[nt*2][0] = tmp[0]; bh[nt*2][1] = tmp[1];
                bh[nt*2+1][0] = tmp[2]; bh[nt*2+1][1] = tmp[3];
                ldsm4(tmp, bd + 16384u);
                bl[nt*2][0] = tmp[0]; bl[nt*2][1] = tmp[1];
                bl[nt*2+1][0] = tmp[2]; bl[nt*2+1][1] = tmp[3];
            }
            #pragma unroll
            for (int mt = 0; mt < 2; mt++)
                #pragma unroll
                for (int nt = 0; nt < 8; nt++) {
                    mma_bf16(d[mt][nt], ah[mt], bh[nt]);
                    mma_bf16(d[mt][nt], al[mt], bh[nt]);
                    mma_bf16(d[mt][nt], ah[mt], bl[nt]);
                }
        }
    }

    // -------- epilogue --------
    int grp = lane >> 2, qd = lane & 3;
    #pragma unroll
    for (int mt = 0; mt < 2; mt++) {
        #pragma unroll
        for (int half = 0; half < 2; half++) {
            int rr = m0w + mt * 16 + grp + half * 8;
            if (MODE >= 2 && rr >= rows) continue;
            int r = row0 + rr;
            float sc = (MODE == 3) ? g_slotscale[r] : 1.f;
            #pragma unroll
            for (int nt = 0; nt < 8; nt++) {
                #pragma unroll
                for (int e2 = 0; e2 < 2; e2++) {
                    int col = col0 + n0w + nt * 8 + qd * 2 + e2;
                    float v = d[mt][nt][half * 2 + e2];
                    if (MODE == 1) {
                        float gt = 1.f / (1.f + __expf(-(v + bias[col])));
                        v = resid[(size_t)r*N + col] + Aelem[(size_t)r*N + col] * gt;
                    } else if (MODE == 3) v *= sc;
                    C[(size_t)r*N + col] = v;
                }
            }
        }
    }
}

// ----------------------------- Householder Q --------------------------------
__global__ void k_house(const float* __restrict__ vs) {
    __shared__ float Q[64][65];
    __shared__ float v[64], w[64];
    __shared__ float vn;
    int tid = threadIdx.x;
    for (int i = tid; i < 4096; i += 256) Q[i>>6][i&63] = ((i>>6)==(i&63)) ? 1.f : 0.f;
    __syncthreads();
    for (int r = 0; r < 32; r++) {
        if (tid < 64) v[tid] = vs[r*64 + tid];
        __syncthreads();
        if (tid == 0) { float s = 0.f; for (int i = 0; i < 64; i++) s += v[i]*v[i]; vn = 2.f / (s + 1e-8f); }
        if (tid < 64) { float s = 0.f; for (int i = 0; i < 64; i++) s += v[i]*Q[i][tid]; w[tid] = s; }
        __syncthreads();
        for (int i = tid; i < 4096; i += 256) { int a = i>>6, b = i&63; Q[a][b] -= vn * v[a] * w[b]; }
        __syncthreads();
    }
    for (int i = tid; i < 4096; i += 256) g_Q[i] = Q[i>>6][i&63];
}

// ----------------------------- RnRoPE ----------------------------------------
__global__ void __launch_bounds__(256) k_rope(const float* __restrict__ rope_pos,
                                              const float* __restrict__ inv_freq) {
    int s = blockIdx.x;
    __shared__ float Q[64][65];
    __shared__ float cs[32], sn[32];
    __shared__ float vec[4][64], tv[4][64];
    int tid = threadIdx.x;
    for (int i = tid; i < 4096; i += 256) Q[i>>6][i&63] = g_Q[i];
    if (tid < 32) {
        float f = 0.f;
        if (tid < 15) f = rope_pos[s*3 + tid/5] * inv_freq[tid % 5];
        cs[tid] = cosf(f); sn[tid] = sinf(f);
    }
    __syncthreads();
    int grp = tid >> 6, lane = tid & 63;
    for (int vb = 0; vb < 32; vb += 4) {
        int vi = vb + grp;
        int h = vi >> 1, isk = vi & 1;
        const float* src = g_qkv + (size_t)s*3*D + isk*D + h*HD;
        vec[grp][lane] = src[lane];
        __syncthreads();
        float t0 = 0.f, t1 = 0.f;
        #pragma unroll
        for (int d = 0; d < 64; d += 2) { t0 += vec[grp][d]*Q[lane][d]; t1 += vec[grp][d+1]*Q[lane][d+1]; }
        tv[grp][lane] = t0 + t1;
        __syncthreads();
        int p = lane & 31;
        float c = cs[p], si = sn[p];
        float rr = (lane < 32) ? (tv[grp][lane]*c - tv[grp][lane+32]*si)
                               : (tv[grp][lane]*c + tv[grp][lane-32]*si);
        __syncthreads();
        vec[grp][lane] = rr;
        __syncthreads();
        float o0 = 0.f, o1 = 0.f;
        #pragma unroll
        for (int d = 0; d < 64; d += 2) { o0 += vec[grp][d]*Q[d][lane]; o1 += vec[grp][d+1]*Q[d+1][lane]; }
        float* dst = (isk ? g_kr : g_qr) + ((size_t)h*S + s)*HD;
        dst[lane] = o0 + o1;
        __syncthreads();
    }
}

// ----------------------------- flash attention -------------------------------
__global__ void __launch_bounds__(256) k_attn() {
    int qt = blockIdx.x, h = blockIdx.y;
    __shared__ float Ks[32][68];
    __shared__ float Vs[32][68];
    __shared__ float Ps[64][33];
    int tid = threadIdx.x, r = tid >> 2, g = tid & 3;

    float qreg[64];
    const float* qrow = g_qr + ((size_t)h*S + qt*64 + r)*HD;
    #pragma unroll
    for (int d = 0; d < 64; d += 4) {
        float4 q4 = *(const float4*)(qrow + d);
        qreg[d] = q4.x; qreg[d+1] = q4.y; qreg[d+2] = q4.z; qreg[d+3] = q4.w;
    }
    float m = -1e30f, l = 0.f, o[16];
    #pragma unroll
    for (int c = 0; c < 16; c++) o[c] = 0.f;

    for (int kt = 0; kt < S; kt += 32) {
        for (int i = tid; i < 32*64; i += 256) {
            int kr = i >> 6, kd = i & 63;
            Ks[kr][kd] = g_kr[((size_t)h*S + kt + kr)*HD + kd];
            Vs[kr][kd] = g_qkv[(size_t)(kt+kr)*3*D + 2*D + h*HD + kd];
        }
        __syncthreads();
        float sc[8];
        #pragma unroll
        for (int kk = 0; kk < 8; kk++) sc[kk] = 0.f;
        #pragma unroll
        for (int d = 0; d < 64; d += 4) {
            #pragma unroll
            for (int kk = 0; kk < 8; kk++) {
                int k = g*8 + kk;
                float4 k4 = *(const float4*)&Ks[k][d];
                sc[kk] += qreg[d]*k4.x + qreg[d+1]*k4.y + qreg[d+2]*k4.z + qreg[d+3]*k4.w;
            }
        }
        float mx = -1e30f;
        #pragma unroll
        for (int kk = 0; kk < 8; kk++) { sc[kk] *= 0.125f; mx = fmaxf(mx, sc[kk]); }
        mx = fmaxf(mx, __shfl_xor_sync(0xffffffffu, mx, 1));
        mx = fmaxf(mx, __shfl_xor_sync(0xffffffffu, mx, 2));
        float mnew = fmaxf(m, mx);
        float corr = __expf(m - mnew);
        float ps = 0.f;
        #pragma unroll
        for (int kk = 0; kk < 8; kk++) {
            float p = __expf(sc[kk] - mnew);
            Ps[r][g*8+kk] = p; ps += p;
        }
        ps += __shfl_xor_sync(0xffffffffu, ps, 1);
        ps += __shfl_xor_sync(0xffffffffu, ps, 2);
        l = l*corr + ps; m = mnew;
        #pragma unroll
        for (int c = 0; c < 16; c++) o[c] *= corr;
        __syncwarp();
        #pragma unroll
        for (int k = 0; k < 32; k++) {
            float p = Ps[r][k];
            #pragma unroll
            for (int c = 0; c < 16; c += 4) {
                float4 v4 = *(const float4*)&Vs[k][g*16+c];
                o[c] += p*v4.x; o[c+1] += p*v4.y; o[c+2] += p*v4.z; o[c+3] += p*v4.w;
            }
        }
        __syncthreads();
    }
    float inv = 1.f / l;
    int sg = qt*64 + r;
    #pragma unroll
    for (int c = 0; c < 16; c++)
        g_attn[(size_t)sg*D + h*HD + g*16 + c] = o[c] * inv;
}

// ----------------------------- router + top-3 --------------------------------
__global__ void k_router(const float* __restrict__ rw, const float* __restrict__ rb) {
    int s = blockIdx.x, tid = threadIdx.x;
    float part[E];
    #pragma unroll
    for (int e = 0; e < E; e++) part[e] = 0.f;
    for (int d = tid; d < D; d += 256) {
        float xv = g_xn2[(size_t)s*D + d];
        const float* wr = rw + (size_t)d*E;
        #pragma unroll
        for (int e = 0; e < E; e++) part[e] += xv * wr[e];
    }
    __shared__ float red[256];
    __shared__ float logit[E];
    for (int e = 0; e < E; e++) {
        red[tid] = part[e]; __syncthreads();
        for (int st = 128; st > 0; st >>= 1) { if (tid < st) red[tid] += red[tid+st]; __syncthreads(); }
        if (tid == 0) logit[e] = red[0] + rb[e];
        __syncthreads();
    }
    if (tid == 0) {
        float sq = 0.f, sg[E];
        #pragma unroll
        for (int e = 0; e < E; e++) { sq += logit[e]*logit[e]; sg[e] = 1.f/(1.f + expf(-logit[e])); }
        atomicAdd(&g_aux[0], sq);
        bool used[E];
        #pragma unroll
        for (int e = 0; e < E; e++) used[e] = false;
        int idx[NACT]; float val[NACT];
        for (int k = 0; k < NACT; k++) {
            float best = -1e30f; int bi = 0;
            for (int e = 0; e < E; e++) if (!used[e] && sg[e] > best) { best = sg[e]; bi = e; }
            used[bi] = true; idx[k] = bi; val[k] = best;
        }
        float sum = val[0] + val[1] + val[2] + 1e-6f;
        for (int k = 0; k < NACT; k++) {
            g_topi[s*NACT + k] = idx[k];
            g_topw[s*NACT + k] = val[k] / sum;
            atomicAdd(&g_counts[idx[k]], 1);
        }
    }
}

__global__ void k_offsets() {
    if (threadIdx.x == 0) {
        int a = 0;
        for (int e = 0; e < E; e++) { g_offsets[e] = a; g_cursor[e] = a; a += g_counts[e]; }
        g_offsets[E] = a;
    }
}

__global__ void k_fill() {
    int s = blockIdx.x*256 + threadIdx.x;
    if (s >= S) return;
    for (int k = 0; k < NACT; k++) {
        int e = g_topi[s*NACT + k];
        int pos = atomicAdd(&g_cursor[e], 1);
        g_rowmap[pos] = s;
        g_slotscale[pos] = g_topw[s*NACT + k];
        g_slotpos[s*NACT + k] = pos;
    }
}

// ----------------------------- SwiGLU (writes bf16 hi/lo) --------------------
__global__ void k_swiglu() {
    size_t i = (size_t)blockIdx.x*256 + threadIdx.x;   // NSLOT*HID total
    size_t row = i >> 12, col = i & (HID-1);
    float h1 = g_h[row*(2*HID) + col];
    float h2 = g_h[row*(2*HID) + HID + col];
    float v = h1 / (1.f + __expf(-h1)) * h2;
    __nv_bfloat16 hh = __float2bfloat16(v);
    g_gh[i] = hh;
    g_gl[i] = __float2bfloat16(v - __bfloat162float(hh));
}

// ----------------------------- final combine ---------------------------------
__global__ void k_final(float* __restrict__ out) {
    size_t i = (size_t)blockIdx.x*256 + threadIdx.x;   // S*D
    int s = (int)(i >> 10);
    int d = (int)(i & (D-1));
    float v = g_xmid[i];
    #pragma unroll
    for (int k = 0; k < NACT; k++) {
        int pos = g_slotpos[s*NACT + k];
        v += g_oslot[(size_t)pos*D + d];
    }
    out[i] = v;
}

__global__ void k_aux(float* out) {
    out[(size_t)S*D] = 0.01f * g_aux[0] / (float)(S*E);
}

// ----------------------------- launch ----------------------------------------
extern "C" void kernel_launch(void* const* d_in, const int* in_sizes, int n_in,
                              void* d_out, int out_size) {
    const float* x        = (const float*)d_in[0];
    const float* rope_pos = (const float*)d_in[1];
    const float* inv_freq = (const float*)d_in[2];
    const float* qkv_w    = (const float*)d_in[3];
    const float* hh_vs    = (const float*)d_in[4];
    const float* out_w    = (const float*)d_in[5];
    const float* gate_w   = (const float*)d_in[6];
    const float* gate_b   = (const float*)d_in[7];
    const float* router_w = (const float*)d_in[8];
    const float* router_b = (const float*)d_in[9];
    const float* w12      = (const float*)d_in[10];
    const float* w3       = (const float*)d_in[11];
    float* out = (float*)d_out;

    cudaFuncSetAttribute(k_gemm_mma<0>, cudaFuncAttributeMaxDynamicSharedMemorySize, SMEM_GEMM);
    cudaFuncSetAttribute(k_gemm_mma<1>, cudaFuncAttributeMaxDynamicSharedMemorySize, SMEM_GEMM);
    cudaFuncSetAttribute(k_gemm_mma<2>, cudaFuncAttributeMaxDynamicSharedMemorySize, SMEM_GEMM);
    cudaFuncSetAttribute(k_gemm_mma<3>, cudaFuncAttributeMaxDynamicSharedMemorySize, SMEM_GEMM);

    float *p_xn, *p_qkv, *p_attn, *p_attnP, *p_xmid, *p_xn2, *p_h, *p_oslot;
    cudaGetSymbolAddress((void**)&p_xn,    g_xn);
    cudaGetSymbolAddress((void**)&p_qkv,   g_qkv);
    cudaGetSymbolAddress((void**)&p_attn,  g_attn);
    cudaGetSymbolAddress((void**)&p_attnP, g_attnP);
    cudaGetSymbolAddress((void**)&p_xmid,  g_xmid);
    cudaGetSymbolAddress((void**)&p_xn2,   g_xn2);
    cudaGetSymbolAddress((void**)&p_h,     g_h);
    cudaGetSymbolAddress((void**)&p_oslot, g_oslot);
    __nv_bfloat16 *b_w12h,*b_w12l,*b_w3h,*b_w3l,*b_qkvh,*b_qkvl,*b_outh,*b_outl,*b_gateh,*b_gatel;
    __nv_bfloat16 *b_xnh,*b_xnl,*b_attnh,*b_attnl,*b_aph,*b_apl,*b_xn2h,*b_xn2l,*b_gh,*b_gl;
    cudaGetSymbolAddress((void**)&b_w12h, g_w12t_h);  cudaGetSymbolAddress((void**)&b_w12l, g_w12t_l);
    cudaGetSymbolAddress((void**)&b_w3h,  g_w3t_h);   cudaGetSymbolAddress((void**)&b_w3l,  g_w3t_l);
    cudaGetSymbolAddress((void**)&b_qkvh, g_qkvt_h);  cudaGetSymbolAddress((void**)&b_qkvl, g_qkvt_l);
    cudaGetSymbolAddress((void**)&b_outh, g_outt_h);  cudaGetSymbolAddress((void**)&b_outl, g_outt_l);
    cudaGetSymbolAddress((void**)&b_gateh,g_gatet_h); cudaGetSymbolAddress((void**)&b_gatel,g_gatet_l);
    cudaGetSymbolAddress((void**)&b_xnh,  g_xn_h);    cudaGetSymbolAddress((void**)&b_xnl,  g_xn_l);
    cudaGetSymbolAddress((void**)&b_attnh,g_attn_h);  cudaGetSymbolAddress((void**)&b_attnl,g_attn_l);
    cudaGetSymbolAddress((void**)&b_aph,  g_attnP_h); cudaGetSymbolAddress((void**)&b_apl,  g_attnP_l);
    cudaGetSymbolAddress((void**)&b_xn2h, g_xn2_h);   cudaGetSymbolAddress((void**)&b_xn2l, g_xn2_l);
    cudaGetSymbolAddress((void**)&b_gh,   g_gh);      cudaGetSymbolAddress((void**)&b_gl,   g_gl);

    k_reset<<<1, 32>>>();
    // weight conversions (transpose + bf16 split)
    k_cvt_t<<<dim3(3*D/32, D/32, 1), dim3(32,8)>>>(qkv_w,  b_qkvh,  b_qkvl,  D, 3*D);
    k_cvt_t<<<dim3(D/32,   D/32, 1), dim3(32,8)>>>(out_w,  b_outh,  b_outl,  D, D);
    k_cvt_t<<<dim3(D/32,   D/32, 1), dim3(32,8)>>>(gate_w, b_gateh, b_gatel, D, D);
    k_cvt_t<<<dim3(2*HID/32, D/32, E), dim3(32,8)>>>(w12, b_w12h, b_w12l, D, 2*HID);
    k_cvt_t<<<dim3(D/32, HID/32,  E), dim3(32,8)>>>(w3,  b_w3h,  b_w3l,  HID, D);

    k_rmsnorm<<<S, 256>>>(x, p_xn);
    k_cvt<<<(S*D+255)/256, 256>>>(p_xn, b_xnh, b_xnl, (size_t)S*D);
    // qkv: [2048,1024] x [1024,3072]
    k_gemm_mma<0><<<dim3(3*D/128, S/128), 256, SMEM_GEMM>>>(b_xnh, b_xnl, b_qkvh, b_qkvl,
        p_qkv, 3*D, D, nullptr, nullptr, nullptr, 0);
    k_house<<<1, 256>>>(hh_vs);
    k_rope<<<S, 256>>>(rope_pos, inv_freq);
    k_attn<<<dim3(S/64, HEADS), 256>>>();
    k_cvt<<<(S*D+255)/256, 256>>>(p_attn, b_attnh, b_attnl, (size_t)S*D);
    // out proj
    k_gemm_mma<0><<<dim3(D/128, S/128), 256, SMEM_GEMM>>>(b_attnh, b_attnl, b_outh, b_outl,
        p_attnP, D, D, nullptr, nullptr, nullptr, 0);
    k_cvt<<<(S*D+255)/256, 256>>>(p_attnP, b_aph, b_apl, (size_t)S*D);
    // gate + residual fused epilogue
    k_gemm_mma<1><<<dim3(D/128, S/128), 256, SMEM_GEMM>>>(b_aph, b_apl, b_gateh, b_gatel,
        p_xmid, D, D, p_attnP, x, gate_b, 0);
    k_rmsnorm<<<S, 256>>>(p_xmid, p_xn2);
    k_cvt<<<(S*D+255)/256, 256>>>(p_xn2, b_xn2h, b_xn2l, (size_t)S*D);
    k_router<<<S, 256>>>(router_w, router_b);
    k_offsets<<<1, 32>>>();
    k_fill<<<(S + 255)/256, 256>>>();
    // MoE stage 1: h = xn2[gathered] @ w12[e]   (grouped M<=6144, N=8192, K=1024)
    k_gemm_mma<2><<<dim3(2*HID/128, E*TPE), 256, SMEM_GEMM>>>(b_xn2h, b_xn2l, b_w12h, b_w12l,
        p_h, 2*HID, D, nullptr, nullptr, nullptr, (long long)2*HID*D);
    k_swiglu<<<(int)((size_t)NSLOT*HID/256), 256>>>();
    // MoE stage 2: oslot = (g @ w3[e]) * slot_weight   (N=1024, K=4096)
    k_gemm_mma<3><<<dim3(D/128, E*TPE), 256, SMEM_GEMM>>>(b_gh, b_gl, b_w3h, b_w3l,
        p_oslot, D, HID, nullptr, nullptr, nullptr, (long long)HID*D);
    k_final<<<(int)((size_t)S*D/256), 256>>>(out);
    if (out_size > S*D) k_aux<<<1, 1>>>(out);
}